// round 3
// baseline (speedup 1.0000x reference)
#include <cuda_runtime.h>
#include <cuda_bf16.h>
#include <cstdint>

// PoseDisentangler: bone_len + bone_dir from H36M skeleton.
// pose_3d: (B=128, N=4096, J=17, 3) fp32, row of 51 floats per (b,n).
// out: [bone_len (B*N*16)] ++ [bone_dir (B*N*48)]
//
// R3: chunked bone loop (4 bones at a time) to cut live registers 78 -> ~44,
// 32-bit indexing, streaming cache hints. Target: occupancy-limited -> BW-limited.

#define ROWS_PER_BLOCK 128
#define ROW_FLOATS 51          // 17 joints * 3
#define NB 16                  // bones
#define EPSF 1e-12f

__global__ __launch_bounds__(ROWS_PER_BLOCK)
void pose_bones_kernel(const float* __restrict__ in,
                       float* __restrict__ len_out,
                       float* __restrict__ dir_out)
{
    __shared__ float s[ROWS_PER_BLOCK * ROW_FLOATS];   // 26112 B

    const int tid = threadIdx.x;
    const int r0  = blockIdx.x * ROWS_PER_BLOCK;       // rows: max 524288, fits int

    // Cooperative vectorized load: 128*51 floats = 1632 float4, base 16B-aligned.
    {
        const float4* __restrict__ gin =
            reinterpret_cast<const float4*>(in + (size_t)r0 * ROW_FLOATS);
        float4* s4 = reinterpret_cast<float4*>(s);
        #pragma unroll
        for (int i = 0; i < 13; ++i) {                 // 13*128 = 1664 slots, 1632 used
            int idx = tid + i * ROWS_PER_BLOCK;
            if (idx < (ROWS_PER_BLOCK * ROW_FLOATS) / 4)   // 1632
                s4[idx] = __ldcs(gin + idx);
        }
    }
    __syncthreads();

    const float* __restrict__ p = s + tid * ROW_FLOATS;  // odd stride -> no bank conflicts

    // H36M parent of bone j (child joint j+1)
    constexpr int PARENT[NB] = {0,1,2,0,4,5,0,7,8,9,8,11,12,8,14,15};

    const int r = r0 + tid;
    float4* __restrict__ lo = reinterpret_cast<float4*>(len_out + r * NB);
    float4* __restrict__ dd = reinterpret_cast<float4*>(dir_out + r * (NB * 3));

    // 4 bones per chunk: 4 len + 12 dir floats live -> 1 + 3 float4 stores.
    // Chunk offsets stay 16B-aligned (r*16 + 4c, r*48 + 12c).
    #pragma unroll
    for (int c = 0; c < NB / 4; ++c) {
        float l[4];
        float d[12];
        #pragma unroll
        for (int jj = 0; jj < 4; ++jj) {
            const int j  = c * 4 + jj;
            const int ch = (j + 1) * 3;
            const int pa = PARENT[j] * 3;
            float vx = p[ch + 0] - p[pa + 0];
            float vy = p[ch + 1] - p[pa + 1];
            float vz = p[ch + 2] - p[pa + 2];
            float ln  = sqrtf(vx * vx + vy * vy + vz * vz);
            float inv = 1.0f / fmaxf(ln, EPSF);
            l[jj]          = ln;
            d[jj * 3 + 0]  = vx * inv;
            d[jj * 3 + 1]  = vy * inv;
            d[jj * 3 + 2]  = vz * inv;
        }
        __stcs(lo + c, make_float4(l[0], l[1], l[2], l[3]));
        __stcs(dd + c * 3 + 0, make_float4(d[0], d[1], d[2],  d[3]));
        __stcs(dd + c * 3 + 1, make_float4(d[4], d[5], d[6],  d[7]));
        __stcs(dd + c * 3 + 2, make_float4(d[8], d[9], d[10], d[11]));
    }
}

extern "C" void kernel_launch(void* const* d_in, const int* in_sizes, int n_in,
                              void* d_out, int out_size)
{
    const float* in = (const float*)d_in[0];
    const int rows = in_sizes[0] / ROW_FLOATS;         // B*N = 524288

    float* len_out = (float*)d_out;
    float* dir_out = len_out + (size_t)rows * NB;

    const int blocks = rows / ROWS_PER_BLOCK;          // exact: 4096
    pose_bones_kernel<<<blocks, ROWS_PER_BLOCK>>>(in, len_out, dir_out);
}

// round 4
// speedup vs baseline: 1.3791x; 1.3791x over previous
#include <cuda_runtime.h>
#include <cuda_bf16.h>
#include <cstdint>

// PoseDisentangler: bone_len + bone_dir from H36M skeleton.
// pose_3d: (B=128, N=4096, J=17, 3) fp32, row of 51 floats per (b,n).
// out: [bone_len (B*N*16)] ++ [bone_dir (B*N*48)]
//
// R4: output-major decomposition. Input staged in SMEM (coalesced float4),
// then threads produce lane-consecutive float4s of len and dir directly ->
// fully coalesced stores (fixes the half-filled-sector store pattern that
// capped DRAM at 47%). Bone recompute (<=2 per dir-float4) is cheap.

#define ROWS_PER_BLOCK 128
#define ROW_FLOATS 51          // 17 joints * 3
#define NB 16                  // bones

// PARENT[j] packed 4 bits per bone: {0,1,2,0,4,5,0,7,8,9,8,11,12,8,14,15}
#define PARENT_PACK 0xFE8CB89870540210ULL
__device__ __forceinline__ int parent_of(int j) {
    return (int)((PARENT_PACK >> (j * 4)) & 15ULL);
}

__global__ __launch_bounds__(ROWS_PER_BLOCK, 8)
void pose_bones_kernel(const float* __restrict__ in,
                       float* __restrict__ len_out,
                       float* __restrict__ dir_out)
{
    __shared__ float s[ROWS_PER_BLOCK * ROW_FLOATS];   // 26112 B

    const int tid = threadIdx.x;

    // Stage input: 1632 float4, coalesced, base 16B-aligned.
    {
        const float4* __restrict__ gin =
            reinterpret_cast<const float4*>(in + (size_t)blockIdx.x * (ROWS_PER_BLOCK * ROW_FLOATS));
        float4* s4 = reinterpret_cast<float4*>(s);
        #pragma unroll
        for (int i = 0; i < 13; ++i) {
            int idx = tid + i * ROWS_PER_BLOCK;
            if (idx < (ROWS_PER_BLOCK * ROW_FLOATS) / 4)   // 1632
                s4[idx] = gin[idx];
        }
    }
    __syncthreads();

    // ---- len: 512 float4 per block, lane-consecutive stores ----
    {
        float4* __restrict__ lo =
            reinterpret_cast<float4*>(len_out) + (size_t)blockIdx.x * (ROWS_PER_BLOCK * NB / 4);
        #pragma unroll
        for (int k = 0; k < 4; ++k) {
            const int m   = tid + k * ROWS_PER_BLOCK;      // float4 index in block
            const int row = m >> 2;
            const int q   = m & 3;                          // bone group
            const float* __restrict__ p = s + row * ROW_FLOATS;
            float l[4];
            #pragma unroll
            for (int jj = 0; jj < 4; ++jj) {
                const int j  = q * 4 + jj;
                const int ch = (j + 1) * 3;
                const int pa = parent_of(j) * 3;
                float vx = p[ch + 0] - p[pa + 0];
                float vy = p[ch + 1] - p[pa + 1];
                float vz = p[ch + 2] - p[pa + 2];
                l[jj] = sqrtf(vx * vx + vy * vy + vz * vz);
            }
            lo[m] = make_float4(l[0], l[1], l[2], l[3]);
        }
    }

    // ---- dir: 1536 float4 per block, lane-consecutive stores ----
    {
        float4* __restrict__ dd =
            reinterpret_cast<float4*>(dir_out) + (size_t)blockIdx.x * (ROWS_PER_BLOCK * NB * 3 / 4);
        #pragma unroll
        for (int k = 0; k < 12; ++k) {
            const int m   = tid + k * ROWS_PER_BLOCK;      // float4 index in block
            const int row = m / 12;
            const int e0  = (m - row * 12) * 4;            // element offset in row's 48
            const int jA  = e0 / 3;                        // first bone touched (<= 14)
            const int off = e0 - jA * 3;                   // 0,1,2
            const float* __restrict__ p = s + row * ROW_FLOATS;

            // bone A = jA
            float ax, ay, az;
            {
                const int ch = (jA + 1) * 3;
                const int pa = parent_of(jA) * 3;
                float vx = p[ch + 0] - p[pa + 0];
                float vy = p[ch + 1] - p[pa + 1];
                float vz = p[ch + 2] - p[pa + 2];
                float inv = rsqrtf(fmaxf(vx*vx + vy*vy + vz*vz, 1e-24f));
                ax = vx * inv; ay = vy * inv; az = vz * inv;
            }
            // bone B = jA + 1 (always valid: jA <= 14)
            float bx, by, bz;
            {
                const int ch = (jA + 2) * 3;
                const int pa = parent_of(jA + 1) * 3;
                float vx = p[ch + 0] - p[pa + 0];
                float vy = p[ch + 1] - p[pa + 1];
                float vz = p[ch + 2] - p[pa + 2];
                float inv = rsqrtf(fmaxf(vx*vx + vy*vy + vz*vz, 1e-24f));
                bx = vx * inv; by = vy * inv; bz = vz * inv;
            }

            // select 4 consecutive elements starting at offset `off` of [A.xyz B.xyz]
            float c0 = (off == 0) ? ax : ((off == 1) ? ay : az);
            float c1 = (off == 0) ? ay : ((off == 1) ? az : bx);
            float c2 = (off == 0) ? az : ((off == 1) ? bx : by);
            float c3 = (off == 0) ? bx : ((off == 1) ? by : bz);
            dd[m] = make_float4(c0, c1, c2, c3);
        }
    }
}

extern "C" void kernel_launch(void* const* d_in, const int* in_sizes, int n_in,
                              void* d_out, int out_size)
{
    const float* in = (const float*)d_in[0];
    const int rows = in_sizes[0] / ROW_FLOATS;         // B*N = 524288

    float* len_out = (float*)d_out;
    float* dir_out = len_out + (size_t)rows * NB;

    const int blocks = rows / ROWS_PER_BLOCK;          // exact: 4096
    pose_bones_kernel<<<blocks, ROWS_PER_BLOCK>>>(in, len_out, dir_out);
}

// round 7
// speedup vs baseline: 1.5039x; 1.0904x over previous
#include <cuda_runtime.h>
#include <cuda_bf16.h>
#include <cstdint>

// PoseDisentangler: bone_len + bone_dir from H36M skeleton.
// pose_3d: (B=128, N=4096, J=17, 3) fp32, row of 51 floats per (b,n).
// out: [bone_len (B*N*16)] ++ [bone_dir (B*N*48)]
//
// R5: 32 rows/block, 4 threads/row (4 bones each, computed ONCE).
// Results staged in small smem buffers, then fully coalesced float4 stores.
// Kills the R4 LDS/recompute explosion while keeping perfect store pattern.

#define ROWS 32                 // rows per block
#define THREADS 128
#define ROW_FLOATS 51           // 17 joints * 3
#define NB 16                   // bones
#define IN_F4 (ROWS * ROW_FLOATS / 4)   // 408 float4 per block
#define DIR_STRIDE 52           // padded dir row stride (floats): <=2-way STS conflicts

// PARENT[j] packed 4 bits per bone: {0,1,2,0,4,5,0,7,8,9,8,11,12,8,14,15}
#define PARENT_PACK 0xFE8CB89870540210ULL
__device__ __forceinline__ int parent_of(int j) {
    return (int)((PARENT_PACK >> (j * 4)) & 15ULL);
}

__global__ __launch_bounds__(THREADS, 12)
void pose_bones_kernel(const float* __restrict__ in,
                       float* __restrict__ len_out,
                       float* __restrict__ dir_out)
{
    __shared__ float s_in[ROWS * ROW_FLOATS];      // 6528 B
    __shared__ float s_len[ROWS * NB];             // 2048 B
    __shared__ float s_dir[ROWS * DIR_STRIDE];     // 6656 B

    const int tid = threadIdx.x;

    // Stage input: 408 float4, coalesced (block base = 6528B * blockIdx, 128B-aligned).
    {
        const float4* __restrict__ gin =
            reinterpret_cast<const float4*>(in) + (size_t)blockIdx.x * IN_F4;
        float4* s4 = reinterpret_cast<float4*>(s_in);
        #pragma unroll
        for (int k = 0; k < 4; ++k) {
            int idx = tid + k * THREADS;
            if (idx < IN_F4)
                s4[idx] = gin[idx];
        }
    }
    __syncthreads();

    // Compute: thread (row = tid>>2, q = tid&3) does bones 4q..4q+3, once each.
    {
        const int row = tid >> 2;
        const int q   = tid & 3;
        const float* __restrict__ p = s_in + row * ROW_FLOATS;

        float l[4];
        float d[12];
        #pragma unroll
        for (int jj = 0; jj < 4; ++jj) {
            const int j  = q * 4 + jj;
            const int ch = (j + 1) * 3;
            const int pa = parent_of(j) * 3;
            float vx = p[ch + 0] - p[pa + 0];
            float vy = p[ch + 1] - p[pa + 1];
            float vz = p[ch + 2] - p[pa + 2];
            float ss  = vx * vx + vy * vy + vz * vz;
            float inv = rsqrtf(fmaxf(ss, 1e-24f));
            l[jj]         = sqrtf(ss);
            d[jj * 3 + 0] = vx * inv;
            d[jj * 3 + 1] = vy * inv;
            d[jj * 3 + 2] = vz * inv;
        }

        // len: 4 floats at s_len[row*16 + 4q] (16B aligned)
        *reinterpret_cast<float4*>(s_len + row * NB + q * 4) =
            make_float4(l[0], l[1], l[2], l[3]);
        // dir: 12 floats at s_dir[row*52 + 12q] (16B aligned)
        float4* sd = reinterpret_cast<float4*>(s_dir + row * DIR_STRIDE + q * 12);
        sd[0] = make_float4(d[0], d[1], d[2],  d[3]);
        sd[1] = make_float4(d[4], d[5], d[6],  d[7]);
        sd[2] = make_float4(d[8], d[9], d[10], d[11]);
    }
    __syncthreads();

    // Coalesced readback -> global.
    // len: block region = 32*16 floats = 128 float4, contiguous.
    {
        const float4* sl4 = reinterpret_cast<const float4*>(s_len);
        float4* __restrict__ lo =
            reinterpret_cast<float4*>(len_out) + (size_t)blockIdx.x * (ROWS * NB / 4);
        lo[tid] = sl4[tid];
    }
    // dir: block region = 32*48 floats = 384 float4, contiguous.
    // smem float4 index for global float4 g: row = g/12 -> g + row (stride 13 vs 12).
    {
        const float4* sd4 = reinterpret_cast<const float4*>(s_dir);
        float4* __restrict__ dd =
            reinterpret_cast<float4*>(dir_out) + (size_t)blockIdx.x * (ROWS * NB * 3 / 4);
        #pragma unroll
        for (int k = 0; k < 3; ++k) {
            int g = tid + k * THREADS;           // 0..383
            int r = g / 12;
            dd[g] = sd4[g + r];                  // r*13 + (g - r*12)
        }
    }
}

extern "C" void kernel_launch(void* const* d_in, const int* in_sizes, int n_in,
                              void* d_out, int out_size)
{
    const float* in = (const float*)d_in[0];
    const int rows = in_sizes[0] / ROW_FLOATS;         // B*N = 524288

    float* len_out = (float*)d_out;
    float* dir_out = len_out + (size_t)rows * NB;

    const int blocks = rows / ROWS;                    // exact: 16384
    pose_bones_kernel<<<blocks, THREADS>>>(in, len_out, dir_out);
}